// round 5
// baseline (speedup 1.0000x reference)
#include <cuda_runtime.h>
#include <cstdint>

#define NN 500000
#define NE 16000000
#define NB_SCAN ((NN + 1023) / 1024)   // 489
#define PROBE_N 1000000

// -------- device scratch (no allocations allowed in kernel_launch) ----------
__device__ int   g_hi_nonzero;         // 0 => adj is int64 (hi words all zero)
__device__ int   g_deg[NN];
__device__ int   g_rowptr[NN + 1];
__device__ int   g_cursor[NN];
__device__ int   g_scan[NN];
__device__ int   g_bsum[NB_SCAN];
__device__ int   g_boff[NB_SCAN];
__device__ float g_dis[NN];
__device__ float g_selfw[NN];
__device__ int2  g_edges[NE];          // {src, __float_as_int(ew)} : 128 MB
__device__ float g_xa[NN];
__device__ float g_xb[NN];

// ----------------------------- dtype probe -----------------------------------
__global__ void probe_zero_kernel() {
    if (blockIdx.x == 0 && threadIdx.x == 0) g_hi_nonzero = 0;
}

// OR-reduce odd int32 words of the first PROBE_N pairs. If adj is int64
// (values in [0,500000), little-endian) these hi-words are all zero; if adj
// is int32 they are random node ids -> virtually surely nonzero.
__global__ void probe_kernel(const int* __restrict__ adj32) {
    int i = blockIdx.x * blockDim.x + threadIdx.x;
    int v = (i < PROBE_N) ? adj32[2 * i + 1] : 0;
    #pragma unroll
    for (int o = 16; o > 0; o >>= 1) v |= __shfl_down_sync(0xffffffffu, v, o);
    if ((threadIdx.x & 31) == 0 && v) atomicOr(&g_hi_nonzero, 1);
}

__device__ __forceinline__ int adj_src(const int* a, int e, int is64) {
    return is64 ? a[2 * e] : a[e];
}
__device__ __forceinline__ int adj_dst(const int* a, int e, int is64) {
    return is64 ? a[2 * (NE + e)] : a[NE + e];
}

// ----------------------------- precompute -----------------------------------
__global__ void zero_deg_kernel() {
    int i = blockIdx.x * blockDim.x + threadIdx.x;
    if (i < NN) g_deg[i] = 0;
}

__global__ void count_kernel(const int* __restrict__ adj) {
    int e = blockIdx.x * blockDim.x + threadIdx.x;
    if (e >= NE) return;
    int is64 = (g_hi_nonzero == 0);
    atomicAdd(&g_deg[adj_dst(adj, e, is64)], 1);
}

__global__ void dis_kernel() {
    int v = blockIdx.x * blockDim.x + threadIdx.x;
    if (v < NN) {
        float di = rsqrtf((float)(g_deg[v] + 1));  // +1 for self-loop
        g_dis[v]   = di;
        g_selfw[v] = di * di;
    }
}

// Inclusive block scan (Hillis-Steele) over g_deg
__global__ void scan1_kernel() {
    __shared__ int sm[1024];
    int t = threadIdx.x;
    int gid = blockIdx.x * 1024 + t;
    int v = (gid < NN) ? g_deg[gid] : 0;
    sm[t] = v;
    __syncthreads();
    for (int off = 1; off < 1024; off <<= 1) {
        int tmp = (t >= off) ? sm[t - off] : 0;
        __syncthreads();
        sm[t] += tmp;
        __syncthreads();
    }
    if (gid < NN) g_scan[gid] = sm[t];
    if (t == 1023) g_bsum[blockIdx.x] = sm[1023];
}

__global__ void scan2_kernel() {
    __shared__ int sm[1024];
    int t = threadIdx.x;
    int v = (t < NB_SCAN) ? g_bsum[t] : 0;
    sm[t] = v;
    __syncthreads();
    for (int off = 1; off < 1024; off <<= 1) {
        int tmp = (t >= off) ? sm[t - off] : 0;
        __syncthreads();
        sm[t] += tmp;
        __syncthreads();
    }
    if (t < NB_SCAN) g_boff[t] = sm[t] - v;   // exclusive offsets per block
}

__global__ void scan3_kernel() {
    int i = blockIdx.x * blockDim.x + threadIdx.x;
    if (i >= NN) return;
    int excl = g_scan[i] - g_deg[i] + g_boff[i >> 10];
    g_rowptr[i] = excl;
    g_cursor[i] = excl;
    if (i == NN - 1) g_rowptr[NN] = excl + g_deg[i];
}

__global__ void scatter_kernel(const int* __restrict__ adj) {
    int e = blockIdx.x * blockDim.x + threadIdx.x;
    if (e >= NE) return;
    int is64 = (g_hi_nonzero == 0);
    int s = adj_src(adj, e, is64);
    int d = adj_dst(adj, e, is64);
    int pos = atomicAdd(&g_cursor[d], 1);
    g_edges[pos] = make_int2(s, __float_as_int(g_dis[s] * g_dis[d]));
}

// ------------------------------ layer kernel --------------------------------
// One warp per destination node. act: 0=identity 1=leaky 2=sigmoid 3=relu 4=final
__global__ void layer_kernel(const float* __restrict__ x0,
                             const float* __restrict__ w,
                             float* __restrict__ out,
                             int layer, int act, int cur_sel, int nxt_sel)
{
    int v = (blockIdx.x * blockDim.x + threadIdx.x) >> 5;
    if (v >= NN) return;
    int lane = threadIdx.x & 31;

    const float* __restrict__ xc =
        (cur_sel == 0) ? g_xa : (cur_sel == 1) ? g_xb : x0;

    int start = g_rowptr[v];
    int end   = g_rowptr[v + 1];

    float sum = 0.0f;
    for (int i = start + lane; i < end; i += 32) {
        int2 e = g_edges[i];
        sum += __int_as_float(e.y) * __ldg(&xc[e.x]);
    }
    #pragma unroll
    for (int o = 16; o > 0; o >>= 1)
        sum += __shfl_down_sync(0xffffffffu, sum, o);

    if (lane != 0) return;

    float h = sum + g_selfw[v] * xc[v];
    float y = (0.7f * h + 0.3f * x0[v]) * w[layer];

    if (act == 4) {
        float s = 1.0f / (1.0f + expf(-y));
        // astype(int) truncates toward zero; values positive and < 2^24,
        // so the truncated integer is exactly representable in fp32.
        out[v] = truncf(500000.0f * s);
        return;
    }
    float r;
    if      (act == 0) r = y;
    else if (act == 1) r = (y > 0.0f) ? y : 0.01f * y;
    else if (act == 2) r = 1.0f / (1.0f + expf(-y));
    else               r = fmaxf(y, 0.0f);

    float* xn = nxt_sel ? g_xb : g_xa;
    xn[v] = r;
}

// ------------------------------- host entry ---------------------------------
extern "C" void kernel_launch(void* const* d_in, const int* in_sizes, int n_in,
                              void* d_out, int out_size)
{
    // Bind inputs by element count, not position: 49 -> w, 500000 -> input,
    // 32000000 (2 x 16M) -> adj. Robust to metadata ordering.
    const float* input = nullptr;
    const float* w     = nullptr;
    const int*   adj   = nullptr;
    for (int i = 0; i < n_in; i++) {
        if      (in_sizes[i] == 49)     w     = (const float*)d_in[i];
        else if (in_sizes[i] == NN)     input = (const float*)d_in[i];
        else                            adj   = (const int*)d_in[i];
    }
    float* out = (float*)d_out;

    int nb_nodes = (NN + 255) / 256;
    int nb_edges = (NE + 255) / 256;
    int nb_probe = (PROBE_N + 255) / 256;

    probe_zero_kernel<<<1, 32>>>();
    probe_kernel  <<<nb_probe, 256>>>(adj);
    zero_deg_kernel<<<nb_nodes, 256>>>();
    count_kernel  <<<nb_edges, 256>>>(adj);
    dis_kernel    <<<nb_nodes, 256>>>();
    scan1_kernel  <<<NB_SCAN, 1024>>>();
    scan2_kernel  <<<1, 1024>>>();
    scan3_kernel  <<<nb_nodes, 256>>>();
    scatter_kernel<<<nb_edges, 256>>>(adj);

    // one warp per node -> 500000 warps -> 62500 blocks of 256 threads
    int nb_layer = (NN * 32 + 255) / 256;
    int cur = -1;  // -1 => read from `input`
    for (int i = 0; i < 49; i++) {
        int act;
        if      (i == 48) act = 4;
        else if (i == 0)  act = 0;
        else if (i == 1 || i == 11 || i == 21 || i == 31 || i == 41) act = 1;
        else if (i == 4 || i == 14 || i == 24 || i == 34 || i == 44) act = 2;
        else act = 3;
        int nxt = (cur == 0) ? 1 : 0;
        layer_kernel<<<nb_layer, 256>>>(input, w, out, i, act, cur, nxt);
        cur = nxt;
    }
}

// round 6
// speedup vs baseline: 1.3748x; 1.3748x over previous
#include <cuda_runtime.h>
#include <cstdint>

#define NN 500000
#define NE 16000000
#define NB_SCAN ((NN + 1023) / 1024)   // 489
#define PROBE_N 1000000

// -------- device scratch (no allocations allowed in kernel_launch) ----------
__device__ int   g_hi_nonzero;         // 0 => adj is int64 (hi words all zero)
__device__ int   g_deg[NN];
__device__ int   g_rowptr[NN + 1];
__device__ int   g_cursor[NN];
__device__ int   g_scan[NN];
__device__ int   g_bsum[NB_SCAN];
__device__ int   g_boff[NB_SCAN];
__device__ float g_dis[NN];
__device__ int   g_src[NE];            // CSR-by-dst src indices : 64 MB
__device__ float g_za[NN];             // z = dis * x  (ping)
__device__ float g_zb[NN];             // z = dis * x  (pong)

// ----------------------------- dtype probe -----------------------------------
__global__ void probe_zero_kernel() {
    if (blockIdx.x == 0 && threadIdx.x == 0) g_hi_nonzero = 0;
}

__global__ void probe_kernel(const int* __restrict__ adj32) {
    int i = blockIdx.x * blockDim.x + threadIdx.x;
    int v = (i < PROBE_N) ? adj32[2 * i + 1] : 0;
    #pragma unroll
    for (int o = 16; o > 0; o >>= 1) v |= __shfl_down_sync(0xffffffffu, v, o);
    if ((threadIdx.x & 31) == 0 && v) atomicOr(&g_hi_nonzero, 1);
}

__device__ __forceinline__ int adj_src(const int* a, int e, int is64) {
    return is64 ? a[2 * e] : a[e];
}
__device__ __forceinline__ int adj_dst(const int* a, int e, int is64) {
    return is64 ? a[2 * (NE + e)] : a[NE + e];
}

// ----------------------------- precompute -----------------------------------
__global__ void zero_deg_kernel() {
    int i = blockIdx.x * blockDim.x + threadIdx.x;
    if (i < NN) g_deg[i] = 0;
}

__global__ void count_kernel(const int* __restrict__ adj) {
    int e = blockIdx.x * blockDim.x + threadIdx.x;
    if (e >= NE) return;
    int is64 = (g_hi_nonzero == 0);
    atomicAdd(&g_deg[adj_dst(adj, e, is64)], 1);
}

// dis + z0 init (z0 = dis * x0)
__global__ void dis_kernel(const float* __restrict__ x0) {
    int v = blockIdx.x * blockDim.x + threadIdx.x;
    if (v < NN) {
        float di = rsqrtf((float)(g_deg[v] + 1));  // +1 for self-loop
        g_dis[v] = di;
        g_za[v]  = di * x0[v];
    }
}

// Inclusive block scan (Hillis-Steele) over g_deg
__global__ void scan1_kernel() {
    __shared__ int sm[1024];
    int t = threadIdx.x;
    int gid = blockIdx.x * 1024 + t;
    int v = (gid < NN) ? g_deg[gid] : 0;
    sm[t] = v;
    __syncthreads();
    for (int off = 1; off < 1024; off <<= 1) {
        int tmp = (t >= off) ? sm[t - off] : 0;
        __syncthreads();
        sm[t] += tmp;
        __syncthreads();
    }
    if (gid < NN) g_scan[gid] = sm[t];
    if (t == 1023) g_bsum[blockIdx.x] = sm[1023];
}

__global__ void scan2_kernel() {
    __shared__ int sm[1024];
    int t = threadIdx.x;
    int v = (t < NB_SCAN) ? g_bsum[t] : 0;
    sm[t] = v;
    __syncthreads();
    for (int off = 1; off < 1024; off <<= 1) {
        int tmp = (t >= off) ? sm[t - off] : 0;
        __syncthreads();
        sm[t] += tmp;
        __syncthreads();
    }
    if (t < NB_SCAN) g_boff[t] = sm[t] - v;   // exclusive offsets per block
}

__global__ void scan3_kernel() {
    int i = blockIdx.x * blockDim.x + threadIdx.x;
    if (i >= NN) return;
    int excl = g_scan[i] - g_deg[i] + g_boff[i >> 10];
    g_rowptr[i] = excl;
    g_cursor[i] = excl;
    if (i == NN - 1) g_rowptr[NN] = excl + g_deg[i];
}

__global__ void scatter_kernel(const int* __restrict__ adj) {
    int e = blockIdx.x * blockDim.x + threadIdx.x;
    if (e >= NE) return;
    int is64 = (g_hi_nonzero == 0);
    int s = adj_src(adj, e, is64);
    int d = adj_dst(adj, e, is64);
    int pos = atomicAdd(&g_cursor[d], 1);
    g_src[pos] = s;
}

// ------------------------------ layer kernel --------------------------------
// One warp per destination node, z-space propagation:
//   h = dis[v] * (sum_{edges} z[src] + z[v]);  y = (0.7h + 0.3 x0[v]) * w
//   z_next = dis[v] * act(y)
// act: 0=identity 1=leaky 2=sigmoid 3=relu 4=final(out = trunc(5e5*sigmoid))
__global__ void layer_kernel(const float* __restrict__ x0,
                             const float* __restrict__ w,
                             float* __restrict__ out,
                             int layer, int act, int cur_sel)
{
    int v = (blockIdx.x * blockDim.x + threadIdx.x) >> 5;
    if (v >= NN) return;
    int lane = threadIdx.x & 31;

    const float* __restrict__ zc = cur_sel ? g_zb : g_za;

    int start = g_rowptr[v];
    int end   = g_rowptr[v + 1];

    float sum = 0.0f;
    for (int i = start + lane; i < end; i += 32)
        sum += __ldg(&zc[__ldg(&g_src[i])]);
    #pragma unroll
    for (int o = 16; o > 0; o >>= 1)
        sum += __shfl_down_sync(0xffffffffu, sum, o);

    if (lane != 0) return;

    float dv = g_dis[v];
    float h  = dv * (sum + zc[v]);
    float y  = (0.7f * h + 0.3f * x0[v]) * w[layer];

    if (act == 4) {
        float s = 1.0f / (1.0f + expf(-y));
        // astype(int) truncates toward zero; value < 2^24 -> exact in fp32.
        out[v] = truncf(500000.0f * s);
        return;
    }
    float r;
    if      (act == 0) r = y;
    else if (act == 1) r = (y > 0.0f) ? y : 0.01f * y;
    else if (act == 2) r = 1.0f / (1.0f + expf(-y));
    else               r = fmaxf(y, 0.0f);

    float* zn = cur_sel ? g_za : g_zb;
    zn[v] = dv * r;
}

// ------------------------------- host entry ---------------------------------
extern "C" void kernel_launch(void* const* d_in, const int* in_sizes, int n_in,
                              void* d_out, int out_size)
{
    // Bind inputs by element count (robust to ordering): 49 -> w, NN -> input,
    // everything else -> adj.
    const float* input = nullptr;
    const float* w     = nullptr;
    const int*   adj   = nullptr;
    for (int i = 0; i < n_in; i++) {
        if      (in_sizes[i] == 49) w     = (const float*)d_in[i];
        else if (in_sizes[i] == NN) input = (const float*)d_in[i];
        else                        adj   = (const int*)d_in[i];
    }
    float* out = (float*)d_out;

    int nb_nodes = (NN + 255) / 256;
    int nb_edges = (NE + 255) / 256;
    int nb_probe = (PROBE_N + 255) / 256;

    probe_zero_kernel<<<1, 32>>>();
    probe_kernel   <<<nb_probe, 256>>>(adj);
    zero_deg_kernel<<<nb_nodes, 256>>>();
    count_kernel   <<<nb_edges, 256>>>(adj);
    dis_kernel     <<<nb_nodes, 256>>>(input);
    scan1_kernel   <<<NB_SCAN, 1024>>>();
    scan2_kernel   <<<1, 1024>>>();
    scan3_kernel   <<<nb_nodes, 256>>>();
    scatter_kernel <<<nb_edges, 256>>>(adj);

    // one warp per node -> 500000 warps -> 62500 blocks of 256 threads
    int nb_layer = (NN * 32 + 255) / 256;
    int cur = 0;   // z0 lives in g_za
    for (int i = 0; i < 49; i++) {
        int act;
        if      (i == 48) act = 4;
        else if (i == 0)  act = 0;
        else if (i == 1 || i == 11 || i == 21 || i == 31 || i == 41) act = 1;
        else if (i == 4 || i == 14 || i == 24 || i == 34 || i == 44) act = 2;
        else act = 3;
        layer_kernel<<<nb_layer, 256>>>(input, w, out, i, act, cur);
        cur ^= 1;
    }
}

// round 7
// speedup vs baseline: 1.7438x; 1.2684x over previous
#include <cuda_runtime.h>
#include <cuda_fp16.h>
#include <cstdint>

#define NN 500000
#define NE 16000000
#define NB_SCAN ((NN + 1023) / 1024)   // 489
#define PROBE_N 1000000

// -------- device scratch (no allocations allowed in kernel_launch) ----------
__device__ int    g_hi_nonzero;        // 0 => adj is int64 (hi words all zero)
__device__ int    g_deg[NN];
__device__ int    g_rowptr[NN + 1];
__device__ int    g_cursor[NN];
__device__ int    g_scan[NN];
__device__ int    g_bsum[NB_SCAN];
__device__ int    g_boff[NB_SCAN];
__device__ float  g_dis[NN];
__device__ int    g_src[NE];           // CSR-by-dst src indices : 64 MB
__device__ __half g_za[NN];            // z = dis * x (ping)  : 1 MB
__device__ __half g_zb[NN];            // z = dis * x (pong)  : 1 MB

// ----------------------------- init + probe ----------------------------------
__global__ void init_kernel() {
    int i = blockIdx.x * blockDim.x + threadIdx.x;
    if (i == 0) g_hi_nonzero = 0;
    if (i < NN) g_deg[i] = 0;
}

// OR-reduce odd int32 words of the first PROBE_N pairs. int64 adj (values in
// [0,500000), LE) -> hi-words all zero; int32 adj -> random ids, surely nonzero.
__global__ void probe_kernel(const int* __restrict__ adj32) {
    int i = blockIdx.x * blockDim.x + threadIdx.x;
    int v = (i < PROBE_N) ? adj32[2 * i + 1] : 0;
    #pragma unroll
    for (int o = 16; o > 0; o >>= 1) v |= __shfl_down_sync(0xffffffffu, v, o);
    if ((threadIdx.x & 31) == 0 && v) atomicOr(&g_hi_nonzero, 1);
}

// ----------------------------- precompute -----------------------------------
__global__ void count_kernel(const int* __restrict__ adj) {
    int e = blockIdx.x * blockDim.x + threadIdx.x;
    if (e >= NE) return;
    int d;
    if (g_hi_nonzero == 0)  // int64: vectorized 8B load, take lo word
        d = ((const int2*)adj)[NE + e].x;
    else
        d = adj[NE + e];
    atomicAdd(&g_deg[d], 1);
}

// dis + z0 init (z0 = dis * x0)
__global__ void dis_kernel(const float* __restrict__ x0) {
    int v = blockIdx.x * blockDim.x + threadIdx.x;
    if (v < NN) {
        float di = rsqrtf((float)(g_deg[v] + 1));  // +1 for self-loop
        g_dis[v] = di;
        g_za[v]  = __float2half(di * x0[v]);
    }
}

// Inclusive block scan (Hillis-Steele) over g_deg
__global__ void scan1_kernel() {
    __shared__ int sm[1024];
    int t = threadIdx.x;
    int gid = blockIdx.x * 1024 + t;
    int v = (gid < NN) ? g_deg[gid] : 0;
    sm[t] = v;
    __syncthreads();
    for (int off = 1; off < 1024; off <<= 1) {
        int tmp = (t >= off) ? sm[t - off] : 0;
        __syncthreads();
        sm[t] += tmp;
        __syncthreads();
    }
    if (gid < NN) g_scan[gid] = sm[t];
    if (t == 1023) g_bsum[blockIdx.x] = sm[1023];
}

__global__ void scan2_kernel() {
    __shared__ int sm[1024];
    int t = threadIdx.x;
    int v = (t < NB_SCAN) ? g_bsum[t] : 0;
    sm[t] = v;
    __syncthreads();
    for (int off = 1; off < 1024; off <<= 1) {
        int tmp = (t >= off) ? sm[t - off] : 0;
        __syncthreads();
        sm[t] += tmp;
        __syncthreads();
    }
    if (t < NB_SCAN) g_boff[t] = sm[t] - v;   // exclusive offsets per block
}

__global__ void scan3_kernel() {
    int i = blockIdx.x * blockDim.x + threadIdx.x;
    if (i >= NN) return;
    int excl = g_scan[i] - g_deg[i] + g_boff[i >> 10];
    g_rowptr[i] = excl;
    g_cursor[i] = excl;
    if (i == NN - 1) g_rowptr[NN] = excl + g_deg[i];
}

__global__ void scatter_kernel(const int* __restrict__ adj) {
    int e = blockIdx.x * blockDim.x + threadIdx.x;
    if (e >= NE) return;
    int s, d;
    if (g_hi_nonzero == 0) {
        s = ((const int2*)adj)[e].x;
        d = ((const int2*)adj)[NE + e].x;
    } else {
        s = adj[e];
        d = adj[NE + e];
    }
    int pos = atomicAdd(&g_cursor[d], 1);
    g_src[pos] = s;
}

// ------------------------------ layer kernel --------------------------------
// One warp per PAIR of consecutive destination nodes (v0 even, v1 = v0+1).
// Edge ranges are contiguous: [s0,e0) ++ [e0,e1). Single stride-32 loop over
// the union keeps all lanes busy and doubles gathers in flight per warp.
// z-space: h = dis[v]*(edge_sum + z[v]); y = (0.7h + 0.3 x0)*w; z' = dis*act(y)
__global__ void layer_kernel(const float* __restrict__ x0,
                             const float* __restrict__ w,
                             float* __restrict__ out,
                             int layer, int act, int cur_sel)
{
    int pair = (blockIdx.x * blockDim.x + threadIdx.x) >> 5;
    int v0 = pair * 2;
    if (v0 >= NN) return;
    int lane = threadIdx.x & 31;

    const __half* __restrict__ zc = cur_sel ? g_zb : g_za;

    int2 r01 = *(const int2*)&g_rowptr[v0];   // {rowptr[v0], rowptr[v0+1]}
    int  s0  = r01.x;
    int  e0  = r01.y;
    int  e1  = g_rowptr[v0 + 2];

    float sum0 = 0.0f, sum1 = 0.0f;
    for (int i = s0 + lane; i < e1; i += 32) {
        float zv = __half2float(__ldg(&zc[__ldg(&g_src[i])]));
        if (i < e0) sum0 += zv; else sum1 += zv;
    }
    #pragma unroll
    for (int o = 16; o > 0; o >>= 1) {
        sum0 += __shfl_down_sync(0xffffffffu, sum0, o);
        sum1 += __shfl_down_sync(0xffffffffu, sum1, o);
    }

    if (lane != 0) return;

    __half2 zself = *(const __half2*)&zc[v0];
    float2  dv    = *(const float2*)&g_dis[v0];
    float2  xv    = *(const float2*)&x0[v0];
    float   wl    = w[layer];

    float h0 = dv.x * (sum0 + __half2float(zself.x));
    float h1 = dv.y * (sum1 + __half2float(zself.y));
    float y0 = (0.7f * h0 + 0.3f * xv.x) * wl;
    float y1 = (0.7f * h1 + 0.3f * xv.y) * wl;

    if (act == 4) {
        // astype(int) truncates toward zero; value < 2^24 -> exact in fp32.
        out[v0]     = truncf(500000.0f / (1.0f + expf(-y0)));
        out[v0 + 1] = truncf(500000.0f / (1.0f + expf(-y1)));
        return;
    }
    float r0, r1;
    if      (act == 0) { r0 = y0; r1 = y1; }
    else if (act == 1) { r0 = (y0 > 0.f) ? y0 : 0.01f * y0;
                         r1 = (y1 > 0.f) ? y1 : 0.01f * y1; }
    else if (act == 2) { r0 = 1.0f / (1.0f + expf(-y0));
                         r1 = 1.0f / (1.0f + expf(-y1)); }
    else               { r0 = fmaxf(y0, 0.f); r1 = fmaxf(y1, 0.f); }

    __half* zn = cur_sel ? g_za : g_zb;
    *(__half2*)&zn[v0] = __floats2half2_rn(dv.x * r0, dv.y * r1);
}

// ------------------------------- host entry ---------------------------------
extern "C" void kernel_launch(void* const* d_in, const int* in_sizes, int n_in,
                              void* d_out, int out_size)
{
    // Bind inputs by element count (robust to ordering).
    const float* input = nullptr;
    const float* w     = nullptr;
    const int*   adj   = nullptr;
    for (int i = 0; i < n_in; i++) {
        if      (in_sizes[i] == 49) w     = (const float*)d_in[i];
        else if (in_sizes[i] == NN) input = (const float*)d_in[i];
        else                        adj   = (const int*)d_in[i];
    }
    float* out = (float*)d_out;

    int nb_nodes = (NN + 255) / 256;
    int nb_edges = (NE + 255) / 256;
    int nb_probe = (PROBE_N + 255) / 256;

    init_kernel   <<<nb_nodes, 256>>>();
    probe_kernel  <<<nb_probe, 256>>>(adj);
    count_kernel  <<<nb_edges, 256>>>(adj);
    dis_kernel    <<<nb_nodes, 256>>>(input);
    scan1_kernel  <<<NB_SCAN, 1024>>>();
    scan2_kernel  <<<1, 1024>>>();
    scan3_kernel  <<<nb_nodes, 256>>>();
    scatter_kernel<<<nb_edges, 256>>>(adj);

    // one warp per node-pair -> 250000 warps -> 31250 blocks of 256 threads
    int nb_layer = ((NN / 2) * 32 + 255) / 256;
    int cur = 0;   // z0 lives in g_za
    for (int i = 0; i < 49; i++) {
        int act;
        if      (i == 48) act = 4;
        else if (i == 0)  act = 0;
        else if (i == 1 || i == 11 || i == 21 || i == 31 || i == 41) act = 1;
        else if (i == 4 || i == 14 || i == 24 || i == 34 || i == 44) act = 2;
        else act = 3;
        layer_kernel<<<nb_layer, 256>>>(input, w, out, i, act, cur);
        cur ^= 1;
    }
}

// round 8
// speedup vs baseline: 3.2088x; 1.8401x over previous
#include <cuda_runtime.h>
#include <cuda_fp16.h>
#include <cstdint>

#define NN 500000
#define NE 16000000
#define PROBE_N 1000000

#define ZT 49152                    // src-tile nodes (96 KB fp16)
#define NT 11                       // tiles: 11*49152 = 540672 >= NN
#define ZPAD (ZT * NT)              // padded z length
#define M2 (NT * NN)                // (tile,dst) counter count = 5,500,000
#define NBLKA ((M2 + 1023) / 1024)  // 5372
#define NBLKB ((NBLKA + 1023) / 1024) // 6

#define GRID_L 123                  // ceil(500000/4096)
#define BLK_L 1024
#define KPT 4                       // consecutive dst nodes per thread
#define SMEM_L (2 * ZT * 2)         // 196608 B double-buffered fp16 tile

// -------- device scratch (no allocations allowed in kernel_launch) ----------
__device__ int      g_hi_nonzero;   // 0 => adj is int64 (hi words all zero)
__device__ int      g_cnt2[M2];     // per-(tile,dst) edge counts
__device__ int      g_sA[M2];       // inclusive block-scan of cnt2
__device__ int      g_off[M2 + 1];  // exclusive offsets (CSR2)
__device__ int      g_cursor2[M2];
__device__ int      g_bsum[NBLKA];
__device__ int      g_bincB[NBLKA];
__device__ int      g_bexclB[NBLKA];
__device__ int      g_bsum2[NBLKB];
__device__ int      g_bexcl2[NBLKB];
__device__ float    g_dis[NN];
__device__ uint16_t g_e16[NE];      // local src within tile : 32 MB
__device__ __half   g_za[ZPAD];     // z = dis*x (ping)
__device__ __half   g_zb[ZPAD];     // z = dis*x (pong)

// ----------------------------- cp.async helpers ------------------------------
__device__ __forceinline__ void cp_async16(void* sdst, const void* gsrc) {
    uint32_t s = (uint32_t)__cvta_generic_to_shared(sdst);
    asm volatile("cp.async.cg.shared.global [%0], [%1], 16;\n" :: "r"(s), "l"(gsrc));
}
__device__ __forceinline__ void cp_commit() {
    asm volatile("cp.async.commit_group;\n" ::);
}
template <int N>
__device__ __forceinline__ void cp_wait() {
    asm volatile("cp.async.wait_group %0;\n" :: "n"(N));
}

// ----------------------------- init + probe ----------------------------------
__global__ void init_kernel() {
    int i = blockIdx.x * blockDim.x + threadIdx.x;
    if (i == 0) g_hi_nonzero = 0;
    if (i < M2) g_cnt2[i] = 0;
}

// int64 adj (values < 5e5, LE) -> odd words all zero; int32 -> random ids.
__global__ void probe_kernel(const int* __restrict__ adj32) {
    int i = blockIdx.x * blockDim.x + threadIdx.x;
    int v = (i < PROBE_N) ? adj32[2 * i + 1] : 0;
    #pragma unroll
    for (int o = 16; o > 0; o >>= 1) v |= __shfl_down_sync(0xffffffffu, v, o);
    if ((threadIdx.x & 31) == 0 && v) atomicOr(&g_hi_nonzero, 1);
}

// ----------------------------- precompute -----------------------------------
__global__ void count2_kernel(const int* __restrict__ adj) {
    int e = blockIdx.x * blockDim.x + threadIdx.x;
    if (e >= NE) return;
    int s, d;
    if (g_hi_nonzero == 0) {
        s = ((const int2*)adj)[e].x;
        d = ((const int2*)adj)[NE + e].x;
    } else {
        s = adj[e];
        d = adj[NE + e];
    }
    atomicAdd(&g_cnt2[(s / ZT) * NN + d], 1);
}

// dis + z0 (deg = sum of per-tile counts)
__global__ void dis_kernel(const float* __restrict__ x0) {
    int v = blockIdx.x * blockDim.x + threadIdx.x;
    if (v >= NN) return;
    int deg = 0;
    #pragma unroll
    for (int t = 0; t < NT; t++) deg += g_cnt2[t * NN + v];
    float di = rsqrtf((float)(deg + 1));  // +1 self-loop
    g_dis[v] = di;
    g_za[v]  = __float2half(di * x0[v]);
}

// generic per-block inclusive scan (1024)
__global__ void scan_blk_kernel(const int* __restrict__ in, int* __restrict__ out,
                                int* __restrict__ bsum, int m) {
    __shared__ int sm[1024];
    int t = threadIdx.x;
    int gid = blockIdx.x * 1024 + t;
    int v = (gid < m) ? in[gid] : 0;
    sm[t] = v;
    __syncthreads();
    for (int off = 1; off < 1024; off <<= 1) {
        int tmp = (t >= off) ? sm[t - off] : 0;
        __syncthreads();
        sm[t] += tmp;
        __syncthreads();
    }
    if (gid < m) out[gid] = sm[t];
    if (t == 1023) bsum[blockIdx.x] = sm[1023];
}

__global__ void scan_tiny_kernel(const int* __restrict__ in, int* __restrict__ outExcl, int m) {
    if (threadIdx.x == 0 && blockIdx.x == 0) {
        int run = 0;
        for (int j = 0; j < m; j++) { outExcl[j] = run; run += in[j]; }
    }
}

__global__ void fixB_kernel() {
    int i = blockIdx.x * blockDim.x + threadIdx.x;
    if (i < NBLKA)
        g_bexclB[i] = g_bincB[i] - g_bsum[i] + g_bexcl2[i >> 10];
}

__global__ void fix_kernel() {
    int g = blockIdx.x * blockDim.x + threadIdx.x;
    if (g >= M2) return;
    int v = g_sA[g] - g_cnt2[g] + g_bexclB[g >> 10];
    g_off[g]     = v;
    g_cursor2[g] = v;
    if (g == M2 - 1) g_off[M2] = v + g_cnt2[g];
}

__global__ void scatter16_kernel(const int* __restrict__ adj) {
    int e = blockIdx.x * blockDim.x + threadIdx.x;
    if (e >= NE) return;
    int s, d;
    if (g_hi_nonzero == 0) {
        s = ((const int2*)adj)[e].x;
        d = ((const int2*)adj)[NE + e].x;
    } else {
        s = adj[e];
        d = adj[NE + e];
    }
    int t = s / ZT;
    int pos = atomicAdd(&g_cursor2[t * NN + d], 1);
    g_e16[pos] = (uint16_t)(s - t * ZT);
}

// ------------------------------ layer kernel --------------------------------
// smem-tiled gather SpMV. CTA covers 4096 consecutive dst nodes (4 per thread).
// Loops over 11 src tiles; z tile double-buffered in smem via cp.async.
// z-space: h = dis[v]*(edge_sum + z[v]); y = (0.7h + 0.3 x0)*w; z' = dis*act(y)
__global__ void __launch_bounds__(BLK_L, 1)
layer_kernel(const float* __restrict__ x0,
             const float* __restrict__ w,
             float* __restrict__ out,
             int layer, int act, int cur_sel)
{
    extern __shared__ __half zb[];   // [2][ZT]
    const __half* __restrict__ zg = cur_sel ? g_zb : g_za;

    int tid = threadIdx.x;
    int n0  = blockIdx.x * (BLK_L * KPT) + tid * KPT;  // NN % 4 == 0: no straddle

    // stage tile 0 into buffer 0
    {
        const char* src = (const char*)(zg);
        char* dst = (char*)(zb);
        #pragma unroll
        for (int i = 0; i < 6; i++) {
            int o = (i * BLK_L + tid) * 16;
            cp_async16(dst + o, src + o);
        }
        cp_commit();
    }

    float acc0 = 0.f, acc1 = 0.f, acc2 = 0.f, acc3 = 0.f;

    for (int t = 0; t < NT; t++) {
        if (t + 1 < NT) {
            const char* src = (const char*)(zg + (t + 1) * ZT);
            char* dst = (char*)(zb + ((t + 1) & 1) * ZT);
            #pragma unroll
            for (int i = 0; i < 6; i++) {
                int o = (i * BLK_L + tid) * 16;
                cp_async16(dst + o, src + o);
            }
        }
        cp_commit();
        cp_wait<1>();      // tile t resident
        __syncthreads();

        if (n0 < NN) {
            const __half* __restrict__ zt = zb + (t & 1) * ZT;
            int g  = t * NN + n0;
            int b0 = __ldg(&g_off[g]);
            int b1 = __ldg(&g_off[g + 1]);
            int b2 = __ldg(&g_off[g + 2]);
            int b3 = __ldg(&g_off[g + 3]);
            int b4 = __ldg(&g_off[g + 4]);
            for (int e = b0; e < b1; e++) acc0 += __half2float(zt[__ldg(&g_e16[e])]);
            for (int e = b1; e < b2; e++) acc1 += __half2float(zt[__ldg(&g_e16[e])]);
            for (int e = b2; e < b3; e++) acc2 += __half2float(zt[__ldg(&g_e16[e])]);
            for (int e = b3; e < b4; e++) acc3 += __half2float(zt[__ldg(&g_e16[e])]);
        }
        __syncthreads();   // protect buffer (t&1) before restage at t+2
    }

    if (n0 >= NN) return;

    float4 dv = *(const float4*)&g_dis[n0];
    float4 xv = *(const float4*)&x0[n0];
    __half2 zs01 = *(const __half2*)&zg[n0];
    __half2 zs23 = *(const __half2*)&zg[n0 + 2];
    float wl = __ldg(&w[layer]);

    float h0 = dv.x * (acc0 + __half2float(zs01.x));
    float h1 = dv.y * (acc1 + __half2float(zs01.y));
    float h2 = dv.z * (acc2 + __half2float(zs23.x));
    float h3 = dv.w * (acc3 + __half2float(zs23.y));
    float y0 = (0.7f * h0 + 0.3f * xv.x) * wl;
    float y1 = (0.7f * h1 + 0.3f * xv.y) * wl;
    float y2 = (0.7f * h2 + 0.3f * xv.z) * wl;
    float y3 = (0.7f * h3 + 0.3f * xv.w) * wl;

    if (act == 4) {
        // astype(int) truncates toward zero; value < 2^24 -> exact in fp32.
        float4 o;
        o.x = truncf(500000.0f / (1.0f + expf(-y0)));
        o.y = truncf(500000.0f / (1.0f + expf(-y1)));
        o.z = truncf(500000.0f / (1.0f + expf(-y2)));
        o.w = truncf(500000.0f / (1.0f + expf(-y3)));
        *(float4*)&out[n0] = o;
        return;
    }
    float r0, r1, r2, r3;
    if      (act == 0) { r0 = y0; r1 = y1; r2 = y2; r3 = y3; }
    else if (act == 1) {
        r0 = (y0 > 0.f) ? y0 : 0.01f * y0;  r1 = (y1 > 0.f) ? y1 : 0.01f * y1;
        r2 = (y2 > 0.f) ? y2 : 0.01f * y2;  r3 = (y3 > 0.f) ? y3 : 0.01f * y3;
    } else if (act == 2) {
        r0 = 1.0f / (1.0f + expf(-y0));  r1 = 1.0f / (1.0f + expf(-y1));
        r2 = 1.0f / (1.0f + expf(-y2));  r3 = 1.0f / (1.0f + expf(-y3));
    } else {
        r0 = fmaxf(y0, 0.f); r1 = fmaxf(y1, 0.f);
        r2 = fmaxf(y2, 0.f); r3 = fmaxf(y3, 0.f);
    }

    __half* zn = cur_sel ? g_za : g_zb;
    *(__half2*)&zn[n0]     = __floats2half2_rn(dv.x * r0, dv.y * r1);
    *(__half2*)&zn[n0 + 2] = __floats2half2_rn(dv.z * r2, dv.w * r3);
}

// ------------------------------- host entry ---------------------------------
extern "C" void kernel_launch(void* const* d_in, const int* in_sizes, int n_in,
                              void* d_out, int out_size)
{
    // Bind inputs by element count (robust to ordering).
    const float* input = nullptr;
    const float* w     = nullptr;
    const int*   adj   = nullptr;
    for (int i = 0; i < n_in; i++) {
        if      (in_sizes[i] == 49) w     = (const float*)d_in[i];
        else if (in_sizes[i] == NN) input = (const float*)d_in[i];
        else                        adj   = (const int*)d_in[i];
    }
    float* out = (float*)d_out;

    cudaFuncSetAttribute(layer_kernel,
                         cudaFuncAttributeMaxDynamicSharedMemorySize, SMEM_L);

    int nb_m2    = (M2 + 255) / 256;
    int nb_nodes = (NN + 255) / 256;
    int nb_edges = (NE + 255) / 256;
    int nb_probe = (PROBE_N + 255) / 256;

    init_kernel     <<<nb_m2, 256>>>();
    probe_kernel    <<<nb_probe, 256>>>(adj);
    count2_kernel   <<<nb_edges, 256>>>(adj);
    dis_kernel      <<<nb_nodes, 256>>>(input);
    scan_blk_kernel <<<NBLKA, 1024>>>(g_cnt2, g_sA, g_bsum, M2);
    scan_blk_kernel <<<NBLKB, 1024>>>(g_bsum, g_bincB, g_bsum2, NBLKA);
    scan_tiny_kernel<<<1, 32>>>(g_bsum2, g_bexcl2, NBLKB);
    fixB_kernel     <<<(NBLKA + 255) / 256, 256>>>();
    fix_kernel      <<<nb_m2, 256>>>();
    scatter16_kernel<<<nb_edges, 256>>>(adj);

    int cur = 0;   // z0 lives in g_za
    for (int i = 0; i < 49; i++) {
        int act;
        if      (i == 48) act = 4;
        else if (i == 0)  act = 0;
        else if (i == 1 || i == 11 || i == 21 || i == 31 || i == 41) act = 1;
        else if (i == 4 || i == 14 || i == 24 || i == 34 || i == 44) act = 2;
        else act = 3;
        layer_kernel<<<GRID_L, BLK_L, SMEM_L>>>(input, w, out, i, act, cur);
        cur ^= 1;
    }
}

// round 9
// speedup vs baseline: 3.6201x; 1.1282x over previous
#include <cuda_runtime.h>
#include <cuda_fp16.h>
#include <cstdint>

#define NN 500000
#define NE 16000000
#define PROBE_N 1000000

#define ZT 49152                    // src-tile nodes (96 KB fp16)
#define NT 11                       // tiles: 11*49152 = 540672 >= NN
#define ZPAD (ZT * NT)              // padded z length
#define M2 (NT * NN)                // (tile,dst) counter count = 5,500,000
#define NBLKA ((M2 + 1023) / 1024)  // 5372
#define NBLKB ((NBLKA + 1023) / 1024) // 6

#define NCHUNK 26                   // dst chunks
#define CS 19232                    // chunk size: 26*19232 = 500032 >= NN
#define BLK_S 1024
#define PD ((CS + BLK_S - 1) / BLK_S)   // 19 dst per thread
#define SMEM_S (ZT * 2)             // 98304 B single tile buffer

// -------- device scratch (no allocations allowed in kernel_launch) ----------
__device__ int      g_hi_nonzero;   // 0 => adj is int64 (hi words all zero)
__device__ int      g_cnt2[M2];     // per-(tile,dst) edge counts
__device__ int      g_sA[M2];       // inclusive block-scan of cnt2
__device__ int      g_off[M2 + 1];  // exclusive offsets (CSR2)
__device__ int      g_cursor2[M2];
__device__ int      g_bsum[NBLKA];
__device__ int      g_bincB[NBLKA];
__device__ int      g_bexclB[NBLKA];
__device__ int      g_bsum2[NBLKB];
__device__ int      g_bexcl2[NBLKB];
__device__ float    g_dis[NN];
__device__ float    g_acc[NN];      // per-layer edge-sum accumulator (fp32)
__device__ uint16_t g_e16[NE];      // local src within tile : 32 MB
__device__ __half   g_za[ZPAD];     // z = dis*x (ping)
__device__ __half   g_zb[ZPAD];     // z = dis*x (pong)

// ----------------------------- cp.async helpers ------------------------------
__device__ __forceinline__ void cp_async16(void* sdst, const void* gsrc) {
    uint32_t s = (uint32_t)__cvta_generic_to_shared(sdst);
    asm volatile("cp.async.cg.shared.global [%0], [%1], 16;\n" :: "r"(s), "l"(gsrc));
}
__device__ __forceinline__ void cp_commit() {
    asm volatile("cp.async.commit_group;\n" ::);
}
template <int N>
__device__ __forceinline__ void cp_wait() {
    asm volatile("cp.async.wait_group %0;\n" :: "n"(N));
}

// ----------------------------- init + probe ----------------------------------
__global__ void init_kernel() {
    int i = blockIdx.x * blockDim.x + threadIdx.x;
    if (i == 0) g_hi_nonzero = 0;
    if (i < M2) g_cnt2[i] = 0;
    if (i < NN) g_acc[i] = 0.0f;
}

// int64 adj (values < 5e5, LE) -> odd words all zero; int32 -> random ids.
__global__ void probe_kernel(const int* __restrict__ adj32) {
    int i = blockIdx.x * blockDim.x + threadIdx.x;
    int v = (i < PROBE_N) ? adj32[2 * i + 1] : 0;
    #pragma unroll
    for (int o = 16; o > 0; o >>= 1) v |= __shfl_down_sync(0xffffffffu, v, o);
    if ((threadIdx.x & 31) == 0 && v) atomicOr(&g_hi_nonzero, 1);
}

// ----------------------------- precompute -----------------------------------
__global__ void count2_kernel(const int* __restrict__ adj) {
    int e = blockIdx.x * blockDim.x + threadIdx.x;
    if (e >= NE) return;
    int s, d;
    if (g_hi_nonzero == 0) {
        s = ((const int2*)adj)[e].x;
        d = ((const int2*)adj)[NE + e].x;
    } else {
        s = adj[e];
        d = adj[NE + e];
    }
    atomicAdd(&g_cnt2[(s / ZT) * NN + d], 1);
}

// dis + z0 (deg = sum of per-tile counts)
__global__ void dis_kernel(const float* __restrict__ x0) {
    int v = blockIdx.x * blockDim.x + threadIdx.x;
    if (v >= NN) return;
    int deg = 0;
    #pragma unroll
    for (int t = 0; t < NT; t++) deg += g_cnt2[t * NN + v];
    float di = rsqrtf((float)(deg + 1));  // +1 self-loop
    g_dis[v] = di;
    g_za[v]  = __float2half(di * x0[v]);
}

// generic per-block inclusive scan (1024)
__global__ void scan_blk_kernel(const int* __restrict__ in, int* __restrict__ out,
                                int* __restrict__ bsum, int m) {
    __shared__ int sm[1024];
    int t = threadIdx.x;
    int gid = blockIdx.x * 1024 + t;
    int v = (gid < m) ? in[gid] : 0;
    sm[t] = v;
    __syncthreads();
    for (int off = 1; off < 1024; off <<= 1) {
        int tmp = (t >= off) ? sm[t - off] : 0;
        __syncthreads();
        sm[t] += tmp;
        __syncthreads();
    }
    if (gid < m) out[gid] = sm[t];
    if (t == 1023) bsum[blockIdx.x] = sm[1023];
}

__global__ void scan_tiny_kernel(const int* __restrict__ in, int* __restrict__ outExcl, int m) {
    if (threadIdx.x == 0 && blockIdx.x == 0) {
        int run = 0;
        for (int j = 0; j < m; j++) { outExcl[j] = run; run += in[j]; }
    }
}

__global__ void fixB_kernel() {
    int i = blockIdx.x * blockDim.x + threadIdx.x;
    if (i < NBLKA)
        g_bexclB[i] = g_bincB[i] - g_bsum[i] + g_bexcl2[i >> 10];
}

__global__ void fix_kernel() {
    int g = blockIdx.x * blockDim.x + threadIdx.x;
    if (g >= M2) return;
    int v = g_sA[g] - g_cnt2[g] + g_bexclB[g >> 10];
    g_off[g]     = v;
    g_cursor2[g] = v;
    if (g == M2 - 1) g_off[M2] = v + g_cnt2[g];
}

__global__ void scatter16_kernel(const int* __restrict__ adj) {
    int e = blockIdx.x * blockDim.x + threadIdx.x;
    if (e >= NE) return;
    int s, d;
    if (g_hi_nonzero == 0) {
        s = ((const int2*)adj)[e].x;
        d = ((const int2*)adj)[NE + e].x;
    } else {
        s = adj[e];
        d = adj[NE + e];
    }
    int t = s / ZT;
    int pos = atomicAdd(&g_cursor2[t * NN + d], 1);
    g_e16[pos] = (uint16_t)(s - t * ZT);
}

// ------------------------------ spmv kernel ---------------------------------
// CTA = (tile t, dst-chunk c). Stages tile t (96 KB) once, walks chunk c's
// edges for tile t (contiguous per thread), accumulates per-dst partials,
// REDG-adds one float per non-empty (dst,tile) into g_acc.
__global__ void __launch_bounds__(BLK_S, 2)
spmv_kernel(int cur_sel)
{
    extern __shared__ __half zt[];   // [ZT]
    int t = blockIdx.x % NT;
    int c = blockIdx.x / NT;
    int tid = threadIdx.x;

    const __half* __restrict__ zg = cur_sel ? g_zb : g_za;

    // stage tile t
    {
        const char* src = (const char*)(zg + t * ZT);
        char* dst = (char*)zt;
        #pragma unroll
        for (int i = 0; i < 6; i++) {
            int o = (i * BLK_S + tid) * 16;
            cp_async16(dst + o, src + o);
        }
        cp_commit();
    }

    int cbase = c * CS;
    int cend  = min(cbase + CS, NN);
    int dbeg  = cbase + tid * PD;
    int dend  = min(dbeg + PD, cend);

    cp_wait<0>();
    __syncthreads();

    if (dbeg >= cend) return;

    int base = t * NN;
    int e = __ldg(&g_off[base + dbeg]);
    for (int d = dbeg; d < dend; d++) {
        int eend = __ldg(&g_off[base + d + 1]);
        float a = 0.0f;
        for (; e < eend; e++)
            a += __half2float(zt[__ldg(&g_e16[e])]);
        if (a != 0.0f) atomicAdd(&g_acc[d], a);
    }
}

// ------------------------------ combine kernel -------------------------------
// h = dis*(acc + z_self); y = (0.7h + 0.3 x0)*w; z' = dis*act(y); acc := 0.
// act: 0=identity 1=leaky 2=sigmoid 3=relu 4=final(out = trunc(5e5*sigmoid))
__global__ void combine_kernel(const float* __restrict__ x0,
                               const float* __restrict__ w,
                               float* __restrict__ out,
                               int layer, int act, int cur_sel)
{
    int v0 = (blockIdx.x * blockDim.x + threadIdx.x) * 4;
    if (v0 >= NN) return;   // NN % 4 == 0

    const __half* __restrict__ zg = cur_sel ? g_zb : g_za;

    float4 av = *(float4*)&g_acc[v0];
    *(float4*)&g_acc[v0] = make_float4(0.f, 0.f, 0.f, 0.f);  // zero for next layer

    float4 dv = *(const float4*)&g_dis[v0];
    float4 xv = *(const float4*)&x0[v0];
    __half2 zs01 = *(const __half2*)&zg[v0];
    __half2 zs23 = *(const __half2*)&zg[v0 + 2];
    float wl = __ldg(&w[layer]);

    float h0 = dv.x * (av.x + __half2float(zs01.x));
    float h1 = dv.y * (av.y + __half2float(zs01.y));
    float h2 = dv.z * (av.z + __half2float(zs23.x));
    float h3 = dv.w * (av.w + __half2float(zs23.y));
    float y0 = (0.7f * h0 + 0.3f * xv.x) * wl;
    float y1 = (0.7f * h1 + 0.3f * xv.y) * wl;
    float y2 = (0.7f * h2 + 0.3f * xv.z) * wl;
    float y3 = (0.7f * h3 + 0.3f * xv.w) * wl;

    if (act == 4) {
        // astype(int) truncates toward zero; value < 2^24 -> exact in fp32.
        float4 o;
        o.x = truncf(500000.0f / (1.0f + expf(-y0)));
        o.y = truncf(500000.0f / (1.0f + expf(-y1)));
        o.z = truncf(500000.0f / (1.0f + expf(-y2)));
        o.w = truncf(500000.0f / (1.0f + expf(-y3)));
        *(float4*)&out[v0] = o;
        return;
    }
    float r0, r1, r2, r3;
    if      (act == 0) { r0 = y0; r1 = y1; r2 = y2; r3 = y3; }
    else if (act == 1) {
        r0 = (y0 > 0.f) ? y0 : 0.01f * y0;  r1 = (y1 > 0.f) ? y1 : 0.01f * y1;
        r2 = (y2 > 0.f) ? y2 : 0.01f * y2;  r3 = (y3 > 0.f) ? y3 : 0.01f * y3;
    } else if (act == 2) {
        r0 = 1.0f / (1.0f + expf(-y0));  r1 = 1.0f / (1.0f + expf(-y1));
        r2 = 1.0f / (1.0f + expf(-y2));  r3 = 1.0f / (1.0f + expf(-y3));
    } else {
        r0 = fmaxf(y0, 0.f); r1 = fmaxf(y1, 0.f);
        r2 = fmaxf(y2, 0.f); r3 = fmaxf(y3, 0.f);
    }

    __half* zn = cur_sel ? g_za : g_zb;
    *(__half2*)&zn[v0]     = __floats2half2_rn(dv.x * r0, dv.y * r1);
    *(__half2*)&zn[v0 + 2] = __floats2half2_rn(dv.z * r2, dv.w * r3);
}

// ------------------------------- host entry ---------------------------------
extern "C" void kernel_launch(void* const* d_in, const int* in_sizes, int n_in,
                              void* d_out, int out_size)
{
    // Bind inputs by element count (robust to ordering).
    const float* input = nullptr;
    const float* w     = nullptr;
    const int*   adj   = nullptr;
    for (int i = 0; i < n_in; i++) {
        if      (in_sizes[i] == 49) w     = (const float*)d_in[i];
        else if (in_sizes[i] == NN) input = (const float*)d_in[i];
        else                        adj   = (const int*)d_in[i];
    }
    float* out = (float*)d_out;

    cudaFuncSetAttribute(spmv_kernel,
                         cudaFuncAttributeMaxDynamicSharedMemorySize, SMEM_S);

    int nb_m2    = (M2 + 255) / 256;
    int nb_nodes = (NN + 255) / 256;
    int nb_edges = (NE + 255) / 256;
    int nb_probe = (PROBE_N + 255) / 256;

    init_kernel     <<<nb_m2, 256>>>();
    probe_kernel    <<<nb_probe, 256>>>(adj);
    count2_kernel   <<<nb_edges, 256>>>(adj);
    dis_kernel      <<<nb_nodes, 256>>>(input);
    scan_blk_kernel <<<NBLKA, 1024>>>(g_cnt2, g_sA, g_bsum, M2);
    scan_blk_kernel <<<NBLKB, 1024>>>(g_bsum, g_bincB, g_bsum2, NBLKA);
    scan_tiny_kernel<<<1, 32>>>(g_bsum2, g_bexcl2, NBLKB);
    fixB_kernel     <<<(NBLKA + 255) / 256, 256>>>();
    fix_kernel      <<<nb_m2, 256>>>();
    scatter16_kernel<<<nb_edges, 256>>>(adj);

    int nb_comb = (NN / 4 + 255) / 256;
    int cur = 0;   // z0 lives in g_za
    for (int i = 0; i < 49; i++) {
        int act;
        if      (i == 48) act = 4;
        else if (i == 0)  act = 0;
        else if (i == 1 || i == 11 || i == 21 || i == 31 || i == 41) act = 1;
        else if (i == 4 || i == 14 || i == 24 || i == 34 || i == 44) act = 2;
        else act = 3;
        spmv_kernel   <<<NT * NCHUNK, BLK_S, SMEM_S>>>(cur);
        combine_kernel<<<nb_comb, 256>>>(input, w, out, i, act, cur);
        cur ^= 1;
    }
}